// round 1
// baseline (speedup 1.0000x reference)
#include <cuda_runtime.h>
#include <math.h>

// Problem constants
// B=4, S=512, E=1024, H=16, DH=64, SCALE = 1/8
#define MROWS 2048            // B*S
#define E3    3072
#define EE    1024
#define SSEQ  512
#define NHEAD 16
#define DHEAD 64
#define NBH   64               // B*H
#define SCALE 0.125f

// ---------------- scratch (device globals; no allocation allowed) -------------
__device__ float g_qkv_v[MROWS * E3];
__device__ float g_qkv_l[MROWS * E3];
__device__ float g_qkv_u[MROWS * E3];
__device__ float g_s_v[NBH * SSEQ * SSEQ];
__device__ float g_s_l[NBH * SSEQ * SSEQ];
__device__ float g_s_u[NBH * SSEQ * SSEQ];
__device__ float g_o_v[MROWS * EE];
__device__ float g_o_l[MROWS * EE];
__device__ float g_o_u[MROWS * EE];

// ============================================================================
// K1 / K5: IBP linear  Y{v,l,u} = X{v,l,u} @ W (+bias), interval x point weight
//   lb' = lb@W+ + ub@W-,  ub' = ub@W+ + lb@W-
// Tile: 64x64 output per CTA, 256 threads, 4x4 microtile, K-step 16.
// ============================================================================
__global__ void __launch_bounds__(256) ibp_linear_kernel(
    const float* __restrict__ Xv, const float* __restrict__ Xl, const float* __restrict__ Xu,
    const float* __restrict__ W, const float* __restrict__ bias,
    float* __restrict__ Yv, float* __restrict__ Yl, float* __restrict__ Yu,
    int M, int N, int K)
{
    __shared__ float sXv[16][64], sXl[16][64], sXu[16][64], sW[16][64];
    const int tid = threadIdx.x;
    const int tx = tid & 15, ty = tid >> 4;
    const int m0 = blockIdx.y * 64, n0 = blockIdx.x * 64;

    float accv[4][4] = {}, accl[4][4] = {}, accu[4][4] = {};

    for (int k0 = 0; k0 < K; k0 += 16) {
        #pragma unroll
        for (int t = 0; t < 4; t++) {
            int e = tid + t * 256;
            int r = e >> 4, c = e & 15;
            int gi = (m0 + r) * K + k0 + c;
            sXv[c][r] = Xv[gi];
            sXl[c][r] = Xl[gi];
            sXu[c][r] = Xu[gi];
        }
        #pragma unroll
        for (int t = 0; t < 4; t++) {
            int e = tid + t * 256;
            int r = e >> 6, c = e & 63;
            sW[r][c] = W[(k0 + r) * N + n0 + c];
        }
        __syncthreads();
        #pragma unroll
        for (int kk = 0; kk < 16; kk++) {
            float av[4], al[4], au[4], bw[4];
            #pragma unroll
            for (int i = 0; i < 4; i++) {
                av[i] = sXv[kk][ty * 4 + i];
                al[i] = sXl[kk][ty * 4 + i];
                au[i] = sXu[kk][ty * 4 + i];
            }
            #pragma unroll
            for (int j = 0; j < 4; j++) bw[j] = sW[kk][tx * 4 + j];
            #pragma unroll
            for (int j = 0; j < 4; j++) {
                float wp = fmaxf(bw[j], 0.0f);
                float wn = fminf(bw[j], 0.0f);
                #pragma unroll
                for (int i = 0; i < 4; i++) {
                    accv[i][j] = fmaf(av[i], bw[j], accv[i][j]);
                    accl[i][j] = fmaf(al[i], wp, fmaf(au[i], wn, accl[i][j]));
                    accu[i][j] = fmaf(au[i], wp, fmaf(al[i], wn, accu[i][j]));
                }
            }
        }
        __syncthreads();
    }
    #pragma unroll
    for (int i = 0; i < 4; i++) {
        int m = m0 + ty * 4 + i;
        #pragma unroll
        for (int j = 0; j < 4; j++) {
            int n = n0 + tx * 4 + j;
            float bb = bias[n];
            size_t idx = (size_t)m * N + n;
            Yv[idx] = accv[i][j] + bb;
            Yl[idx] = accl[i][j] + bb;
            Yu[idx] = accu[i][j] + bb;
        }
    }
}

// ============================================================================
// K2: interval scores  S = (q*SCALE) @ k^T  (interval x interval, 4-way clamp
// collapsed to sign-selects on the B operand)
// ============================================================================
__global__ void __launch_bounds__(256) ibp_scores_kernel(
    const float* __restrict__ Qv, const float* __restrict__ Ql, const float* __restrict__ Qu,
    float* __restrict__ Sv, float* __restrict__ Sl, float* __restrict__ Su)
{
    __shared__ float sAv[16][64], sAl[16][64], sAu[16][64];
    __shared__ float sBv[16][64], sBl[16][64], sBu[16][64];
    const int tid = threadIdx.x;
    const int tx = tid & 15, ty = tid >> 4;
    const int bh = blockIdx.z;
    const int b = bh >> 4, h = bh & 15;
    const int m0 = blockIdx.y * 64, n0 = blockIdx.x * 64;
    const int qcol = h * DHEAD;
    const int kcol = EE + h * DHEAD;

    float accv[4][4] = {}, accl[4][4] = {}, accu[4][4] = {};

    for (int k0 = 0; k0 < DHEAD; k0 += 16) {
        #pragma unroll
        for (int t = 0; t < 4; t++) {
            int e = tid + t * 256;
            int r = e >> 4, c = e & 15;
            int gia = (b * SSEQ + m0 + r) * E3 + qcol + k0 + c;
            sAv[c][r] = Qv[gia] * SCALE;
            sAl[c][r] = Ql[gia] * SCALE;
            sAu[c][r] = Qu[gia] * SCALE;
            int gib = (b * SSEQ + n0 + r) * E3 + kcol + k0 + c;
            sBv[c][r] = Qv[gib];
            sBl[c][r] = Ql[gib];
            sBu[c][r] = Qu[gib];
        }
        __syncthreads();
        #pragma unroll
        for (int kk = 0; kk < 16; kk++) {
            float av[4], pal[4], nal[4], pau[4], nau[4];
            #pragma unroll
            for (int i = 0; i < 4; i++) {
                av[i] = sAv[kk][ty * 4 + i];
                float al = sAl[kk][ty * 4 + i];
                float au = sAu[kk][ty * 4 + i];
                pal[i] = fmaxf(al, 0.0f); nal[i] = fminf(al, 0.0f);
                pau[i] = fmaxf(au, 0.0f); nau[i] = fminf(au, 0.0f);
            }
            #pragma unroll
            for (int j = 0; j < 4; j++) {
                float bv = sBv[kk][tx * 4 + j];
                float bl = sBl[kk][tx * 4 + j];
                float bu = sBu[kk][tx * 4 + j];
                bool lp = (bl >= 0.0f);
                bool up = (bu >= 0.0f);
                #pragma unroll
                for (int i = 0; i < 4; i++) {
                    accv[i][j] = fmaf(av[i], bv, accv[i][j]);
                    float cl = lp ? pal[i] : pau[i];
                    float cu = up ? nal[i] : nau[i];
                    accl[i][j] = fmaf(cl, bl, fmaf(cu, bu, accl[i][j]));
                    float dl = up ? pau[i] : pal[i];
                    float du = lp ? nau[i] : nal[i];
                    accu[i][j] = fmaf(dl, bu, fmaf(du, bl, accu[i][j]));
                }
            }
        }
        __syncthreads();
    }
    #pragma unroll
    for (int i = 0; i < 4; i++) {
        int m = m0 + ty * 4 + i;
        #pragma unroll
        for (int j = 0; j < 4; j++) {
            int n = n0 + tx * 4 + j;
            size_t idx = ((size_t)bh * SSEQ + m) * SSEQ + n;
            Sv[idx] = accv[i][j];
            Sl[idx] = accl[i][j];
            Su[idx] = accu[i][j];
        }
    }
}

// ============================================================================
// K3: IBP softmax, in-place on the score buffers. One warp per row of 512.
//   pl = e_l / (S_u - e_u + e_l), pu = e_u / (S_l - e_l + e_u), clipped [0,1]
// ============================================================================
__global__ void __launch_bounds__(256) ibp_softmax_kernel(
    float* __restrict__ Sv, float* __restrict__ Sl, float* __restrict__ Su)
{
    const int row  = blockIdx.x * 8 + (threadIdx.x >> 5);
    const int lane = threadIdx.x & 31;
    size_t base = (size_t)row * SSEQ + lane;

    float v[16], l[16], u[16];
    #pragma unroll
    for (int t = 0; t < 16; t++) {
        v[t] = Sv[base + t * 32];
        l[t] = Sl[base + t * 32];
        u[t] = Su[base + t * 32];
    }
    float mu = -INFINITY, mv = -INFINITY;
    #pragma unroll
    for (int t = 0; t < 16; t++) { mu = fmaxf(mu, u[t]); mv = fmaxf(mv, v[t]); }
    #pragma unroll
    for (int o = 16; o > 0; o >>= 1) {
        mu = fmaxf(mu, __shfl_xor_sync(0xFFFFFFFFu, mu, o));
        mv = fmaxf(mv, __shfl_xor_sync(0xFFFFFFFFu, mv, o));
    }
    float sumv = 0.0f, suml = 0.0f, sumu = 0.0f;
    #pragma unroll
    for (int t = 0; t < 16; t++) {
        v[t] = __expf(v[t] - mv);
        l[t] = __expf(l[t] - mu);
        u[t] = __expf(u[t] - mu);
        sumv += v[t]; suml += l[t]; sumu += u[t];
    }
    #pragma unroll
    for (int o = 16; o > 0; o >>= 1) {
        sumv += __shfl_xor_sync(0xFFFFFFFFu, sumv, o);
        suml += __shfl_xor_sync(0xFFFFFFFFu, suml, o);
        sumu += __shfl_xor_sync(0xFFFFFFFFu, sumu, o);
    }
    #pragma unroll
    for (int t = 0; t < 16; t++) {
        float pv = v[t] / sumv;
        float pl = l[t] / (sumu - u[t] + l[t]);
        float pu = u[t] / (suml - l[t] + u[t]);
        pl = fminf(fmaxf(pl, 0.0f), 1.0f);
        pu = fminf(fmaxf(pu, 0.0f), 1.0f);
        Sv[base + t * 32] = pv;
        Sl[base + t * 32] = pl;
        Su[base + t * 32] = pu;
    }
}

// ============================================================================
// K4: O = P @ V (interval x interval), P >= 0 so neg(P)=0:
//   lb = pl @ pos(vl) + pu @ neg(vl), ub = pu @ pos(vu) + pl @ neg(vu)
// Output merged back to [B,S,E] layout.
// ============================================================================
__global__ void __launch_bounds__(256) ibp_pv_kernel(
    const float* __restrict__ Pv, const float* __restrict__ Pl, const float* __restrict__ Pu,
    const float* __restrict__ Qv, const float* __restrict__ Ql, const float* __restrict__ Qu,
    float* __restrict__ Ov, float* __restrict__ Ol, float* __restrict__ Ou)
{
    __shared__ float sPv[16][64], sPl[16][64], sPu[16][64];
    __shared__ float sVv[16][64], sVl[16][64], sVu[16][64];
    const int tid = threadIdx.x;
    const int tx = tid & 15, ty = tid >> 4;
    const int bh = blockIdx.z;
    const int b = bh >> 4, h = bh & 15;
    const int m0 = blockIdx.y * 64;
    const int vcol = 2 * EE + h * DHEAD;
    size_t pbase = (size_t)bh * SSEQ * SSEQ;

    float accv[4][4] = {}, accl[4][4] = {}, accu[4][4] = {};

    for (int k0 = 0; k0 < SSEQ; k0 += 16) {
        #pragma unroll
        for (int t = 0; t < 4; t++) {
            int e = tid + t * 256;
            int r = e >> 4, c = e & 15;
            size_t gip = pbase + (size_t)(m0 + r) * SSEQ + k0 + c;
            sPv[c][r] = Pv[gip];
            sPl[c][r] = Pl[gip];
            sPu[c][r] = Pu[gip];
        }
        #pragma unroll
        for (int t = 0; t < 4; t++) {
            int e = tid + t * 256;
            int r = e >> 6, c = e & 63;
            int gi = (b * SSEQ + k0 + r) * E3 + vcol + c;
            sVv[r][c] = Qv[gi];
            sVl[r][c] = Ql[gi];
            sVu[r][c] = Qu[gi];
        }
        __syncthreads();
        #pragma unroll
        for (int kk = 0; kk < 16; kk++) {
            float pv[4], pl[4], pu[4];
            #pragma unroll
            for (int i = 0; i < 4; i++) {
                pv[i] = sPv[kk][ty * 4 + i];
                pl[i] = sPl[kk][ty * 4 + i];
                pu[i] = sPu[kk][ty * 4 + i];
            }
            #pragma unroll
            for (int j = 0; j < 4; j++) {
                float bv = sVv[kk][tx * 4 + j];
                float bl = sVl[kk][tx * 4 + j];
                float bu = sVu[kk][tx * 4 + j];
                bool lp = (bl >= 0.0f);
                bool up = (bu >= 0.0f);
                #pragma unroll
                for (int i = 0; i < 4; i++) {
                    accv[i][j] = fmaf(pv[i], bv, accv[i][j]);
                    accl[i][j] = fmaf(lp ? pl[i] : pu[i], bl, accl[i][j]);
                    accu[i][j] = fmaf(up ? pu[i] : pl[i], bu, accu[i][j]);
                }
            }
        }
        __syncthreads();
    }
    #pragma unroll
    for (int i = 0; i < 4; i++) {
        int m = m0 + ty * 4 + i;
        #pragma unroll
        for (int j = 0; j < 4; j++) {
            int d = tx * 4 + j;
            size_t idx = (size_t)(b * SSEQ + m) * EE + h * DHEAD + d;
            Ov[idx] = accv[i][j];
            Ol[idx] = accl[i][j];
            Ou[idx] = accu[i][j];
        }
    }
}

// ============================================================================
// Launch
// Inputs (metadata order): x_val, x_lb, x_ub, in_proj_w, in_proj_b,
//                          out_proj_w, out_proj_b
// Output: [3, B, S, E] fp32
// ============================================================================
extern "C" void kernel_launch(void* const* d_in, const int* in_sizes, int n_in,
                              void* d_out, int out_size) {
    const float* xv = (const float*)d_in[0];
    const float* xl = (const float*)d_in[1];
    const float* xu = (const float*)d_in[2];
    const float* Wi = (const float*)d_in[3];
    const float* bi = (const float*)d_in[4];
    const float* Wo = (const float*)d_in[5];
    const float* bo = (const float*)d_in[6];
    float* out = (float*)d_out;

    float *qv, *ql, *qu, *sv, *sl, *su, *ov, *ol, *ou;
    cudaGetSymbolAddress((void**)&qv, g_qkv_v);
    cudaGetSymbolAddress((void**)&ql, g_qkv_l);
    cudaGetSymbolAddress((void**)&qu, g_qkv_u);
    cudaGetSymbolAddress((void**)&sv, g_s_v);
    cudaGetSymbolAddress((void**)&sl, g_s_l);
    cudaGetSymbolAddress((void**)&su, g_s_u);
    cudaGetSymbolAddress((void**)&ov, g_o_v);
    cudaGetSymbolAddress((void**)&ol, g_o_l);
    cudaGetSymbolAddress((void**)&ou, g_o_u);

    dim3 blk(256);

    // K1: qkv = ibp_linear(x, in_proj)   [2048 x 3072]
    ibp_linear_kernel<<<dim3(E3 / 64, MROWS / 64), blk>>>(
        xv, xl, xu, Wi, bi, qv, ql, qu, MROWS, E3, EE);

    // K2: interval scores per (b,h)      [64 x 512 x 512]
    ibp_scores_kernel<<<dim3(SSEQ / 64, SSEQ / 64, NBH), blk>>>(
        qv, ql, qu, sv, sl, su);

    // K3: IBP softmax in-place, warp per row
    ibp_softmax_kernel<<<(NBH * SSEQ) / 8, blk>>>(sv, sl, su);

    // K4: O = P @ V, merged to [B,S,E]
    ibp_pv_kernel<<<dim3(1, SSEQ / 64, NBH), blk>>>(
        sv, sl, su, qv, ql, qu, ov, ol, ou);

    // K5: y = ibp_linear(O, out_proj) -> d_out [3][2048][1024]
    ibp_linear_kernel<<<dim3(EE / 64, MROWS / 64), blk>>>(
        ov, ol, ou, Wo, bo,
        out, out + (size_t)MROWS * EE, out + 2 * (size_t)MROWS * EE,
        MROWS, EE, EE);
}

// round 2
// speedup vs baseline: 1.7220x; 1.7220x over previous
#include <cuda_runtime.h>
#include <math.h>

// Problem constants: B=4, S=512, E=1024, H=16, DH=64, SCALE = 1/8
#define MROWS 2048
#define E3    3072
#define EE    1024
#define SSEQ  512
#define NHEAD 16
#define DHEAD 64
#define NBH   64
#define SCALE 0.125f

// ---------------- scratch (device globals) -------------
__device__ float g_qkv_v[MROWS * E3];
__device__ float g_qkv_l[MROWS * E3];
__device__ float g_qkv_u[MROWS * E3];
__device__ float g_s_v[NBH * SSEQ * SSEQ];
__device__ float g_s_l[NBH * SSEQ * SSEQ];
__device__ float g_s_u[NBH * SSEQ * SSEQ];
__device__ float g_o_v[MROWS * EE];
__device__ float g_o_c[MROWS * EE];   // center
__device__ float g_o_r[MROWS * EE];   // radius

__device__ __forceinline__ void ld4(float* d, const float* s) {
    float4 t = *(const float4*)s;
    d[0] = t.x; d[1] = t.y; d[2] = t.z; d[3] = t.w;
}

// ============================================================================
// K1 / K5: IBP linear via center-radius (EXACT for interval x point weight):
//   val' = v@W + b;  c' = c@W;  r' = r@|W|;  lb' = c'-r'+b;  ub' = c'+r'+b
// CONV=true: Xa=lb, Xb=ub converted to (c,r) on load. CONV=false: Xa=c, Xb=r.
// Tile 64x64, 256 threads, 4x4 microtile, 2 CTAs/SM.
// ============================================================================
template<bool CONV>
__global__ void __launch_bounds__(256, 2) ibp_linear_cr(
    const float* __restrict__ Xv, const float* __restrict__ Xa, const float* __restrict__ Xb,
    const float* __restrict__ W, const float* __restrict__ bias,
    float* __restrict__ Yv, float* __restrict__ Yl, float* __restrict__ Yu,
    int M, int N, int K)
{
    __shared__ float sXv[16][68], sXc[16][68], sXr[16][68];
    __shared__ float sW[16][64];
    const int tid = threadIdx.x;
    const int tx = tid & 15, ty = tid >> 4;
    const int m0 = blockIdx.y * 64, n0 = blockIdx.x * 64;

    float accv[4][4] = {}, accc[4][4] = {}, accr[4][4] = {};

    for (int k0 = 0; k0 < K; k0 += 16) {
        #pragma unroll
        for (int t = 0; t < 4; t++) {
            int e = tid + t * 256;
            int r = e >> 4, c = e & 15;
            size_t gi = (size_t)(m0 + r) * K + k0 + c;
            float a = Xa[gi], b2 = Xb[gi];
            float cc, rr;
            if (CONV) { cc = 0.5f * (a + b2); rr = 0.5f * (b2 - a); }
            else      { cc = a; rr = b2; }
            sXv[c][r] = Xv[gi];
            sXc[c][r] = cc;
            sXr[c][r] = rr;
        }
        #pragma unroll
        for (int t = 0; t < 4; t++) {
            int e = tid + t * 256;
            int r = e >> 6, c = e & 63;
            sW[r][c] = W[(size_t)(k0 + r) * N + n0 + c];
        }
        __syncthreads();
        #pragma unroll
        for (int kk = 0; kk < 16; kk++) {
            float av[4], ac[4], ar[4], bw[4], ba[4];
            ld4(av, &sXv[kk][ty * 4]);
            ld4(ac, &sXc[kk][ty * 4]);
            ld4(ar, &sXr[kk][ty * 4]);
            ld4(bw, &sW[kk][tx * 4]);
            #pragma unroll
            for (int j = 0; j < 4; j++) ba[j] = fabsf(bw[j]);
            #pragma unroll
            for (int j = 0; j < 4; j++) {
                #pragma unroll
                for (int i = 0; i < 4; i++) {
                    accv[i][j] = fmaf(av[i], bw[j], accv[i][j]);
                    accc[i][j] = fmaf(ac[i], bw[j], accc[i][j]);
                    accr[i][j] = fmaf(ar[i], ba[j], accr[i][j]);
                }
            }
        }
        __syncthreads();
    }
    #pragma unroll
    for (int i = 0; i < 4; i++) {
        int m = m0 + ty * 4 + i;
        #pragma unroll
        for (int j = 0; j < 4; j++) {
            int n = n0 + tx * 4 + j;
            float bb = bias[n];
            size_t idx = (size_t)m * N + n;
            Yv[idx] = accv[i][j] + bb;
            Yl[idx] = (accc[i][j] - accr[i][j]) + bb;
            Yu[idx] = (accc[i][j] + accr[i][j]) + bb;
        }
    }
}

// ============================================================================
// K2: interval scores  S = (q*SCALE) @ k^T  (exact 4-corner bounds via
// sign-selects on the B operand)
// ============================================================================
__global__ void __launch_bounds__(256, 2) ibp_scores_kernel(
    const float* __restrict__ Qv, const float* __restrict__ Ql, const float* __restrict__ Qu,
    float* __restrict__ Sv, float* __restrict__ Sl, float* __restrict__ Su)
{
    __shared__ float sAv[16][68], sAl[16][68], sAu[16][68];
    __shared__ float sBv[16][68], sBl[16][68], sBu[16][68];
    const int tid = threadIdx.x;
    const int tx = tid & 15, ty = tid >> 4;
    const int bh = blockIdx.z;
    const int b = bh >> 4, h = bh & 15;
    const int m0 = blockIdx.y * 64, n0 = blockIdx.x * 64;
    const int qcol = h * DHEAD;
    const int kcol = EE + h * DHEAD;

    float accv[4][4] = {}, accl[4][4] = {}, accu[4][4] = {};

    for (int k0 = 0; k0 < DHEAD; k0 += 16) {
        #pragma unroll
        for (int t = 0; t < 4; t++) {
            int e = tid + t * 256;
            int r = e >> 4, c = e & 15;
            size_t gia = (size_t)(b * SSEQ + m0 + r) * E3 + qcol + k0 + c;
            sAv[c][r] = Qv[gia] * SCALE;
            sAl[c][r] = Ql[gia] * SCALE;
            sAu[c][r] = Qu[gia] * SCALE;
            size_t gib = (size_t)(b * SSEQ + n0 + r) * E3 + kcol + k0 + c;
            sBv[c][r] = Qv[gib];
            sBl[c][r] = Ql[gib];
            sBu[c][r] = Qu[gib];
        }
        __syncthreads();
        #pragma unroll
        for (int kk = 0; kk < 16; kk++) {
            float av[4], al4[4], au4[4];
            float pal[4], nal[4], pau[4], nau[4];
            ld4(av, &sAv[kk][ty * 4]);
            ld4(al4, &sAl[kk][ty * 4]);
            ld4(au4, &sAu[kk][ty * 4]);
            #pragma unroll
            for (int i = 0; i < 4; i++) {
                pal[i] = fmaxf(al4[i], 0.0f); nal[i] = fminf(al4[i], 0.0f);
                pau[i] = fmaxf(au4[i], 0.0f); nau[i] = fminf(au4[i], 0.0f);
            }
            float bv[4], bl[4], bu[4];
            ld4(bv, &sBv[kk][tx * 4]);
            ld4(bl, &sBl[kk][tx * 4]);
            ld4(bu, &sBu[kk][tx * 4]);
            #pragma unroll
            for (int j = 0; j < 4; j++) {
                bool lp = (bl[j] >= 0.0f);
                bool up = (bu[j] >= 0.0f);
                #pragma unroll
                for (int i = 0; i < 4; i++) {
                    accv[i][j] = fmaf(av[i], bv[j], accv[i][j]);
                    float cl = lp ? pal[i] : pau[i];
                    float cu = up ? nal[i] : nau[i];
                    accl[i][j] = fmaf(cl, bl[j], fmaf(cu, bu[j], accl[i][j]));
                    float dl = up ? pau[i] : pal[i];
                    float du = lp ? nau[i] : nal[i];
                    accu[i][j] = fmaf(dl, bu[j], fmaf(du, bl[j], accu[i][j]));
                }
            }
        }
        __syncthreads();
    }
    #pragma unroll
    for (int i = 0; i < 4; i++) {
        int m = m0 + ty * 4 + i;
        #pragma unroll
        for (int j = 0; j < 4; j++) {
            int n = n0 + tx * 4 + j;
            size_t idx = ((size_t)bh * SSEQ + m) * SSEQ + n;
            Sv[idx] = accv[i][j];
            Sl[idx] = accl[i][j];
            Su[idx] = accu[i][j];
        }
    }
}

// ============================================================================
// K3: IBP softmax, in-place. One warp per row of 512.
// ============================================================================
__global__ void __launch_bounds__(256) ibp_softmax_kernel(
    float* __restrict__ Sv, float* __restrict__ Sl, float* __restrict__ Su)
{
    const int row  = blockIdx.x * 8 + (threadIdx.x >> 5);
    const int lane = threadIdx.x & 31;
    size_t base = (size_t)row * SSEQ + lane;

    float v[16], l[16], u[16];
    #pragma unroll
    for (int t = 0; t < 16; t++) {
        v[t] = Sv[base + t * 32];
        l[t] = Sl[base + t * 32];
        u[t] = Su[base + t * 32];
    }
    float mu = -INFINITY, mv = -INFINITY;
    #pragma unroll
    for (int t = 0; t < 16; t++) { mu = fmaxf(mu, u[t]); mv = fmaxf(mv, v[t]); }
    #pragma unroll
    for (int o = 16; o > 0; o >>= 1) {
        mu = fmaxf(mu, __shfl_xor_sync(0xFFFFFFFFu, mu, o));
        mv = fmaxf(mv, __shfl_xor_sync(0xFFFFFFFFu, mv, o));
    }
    float sumv = 0.0f, suml = 0.0f, sumu = 0.0f;
    #pragma unroll
    for (int t = 0; t < 16; t++) {
        v[t] = __expf(v[t] - mv);
        l[t] = __expf(l[t] - mu);
        u[t] = __expf(u[t] - mu);
        sumv += v[t]; suml += l[t]; sumu += u[t];
    }
    #pragma unroll
    for (int o = 16; o > 0; o >>= 1) {
        sumv += __shfl_xor_sync(0xFFFFFFFFu, sumv, o);
        suml += __shfl_xor_sync(0xFFFFFFFFu, suml, o);
        sumu += __shfl_xor_sync(0xFFFFFFFFu, sumu, o);
    }
    #pragma unroll
    for (int t = 0; t < 16; t++) {
        float pv = v[t] / sumv;
        float pl = l[t] / (sumu - u[t] + l[t]);
        float pu = u[t] / (suml - l[t] + u[t]);
        pl = fminf(fmaxf(pl, 0.0f), 1.0f);
        pu = fminf(fmaxf(pu, 0.0f), 1.0f);
        Sv[base + t * 32] = pv;
        Sl[base + t * 32] = pl;
        Su[base + t * 32] = pu;
    }
}

// ============================================================================
// K4: O = P @ V (interval x interval, P >= 0). Outputs val + (center,radius)
// for the CR out_proj. Merged back to [B,S,E].
// ============================================================================
__global__ void __launch_bounds__(256, 2) ibp_pv_kernel(
    const float* __restrict__ Pv, const float* __restrict__ Pl, const float* __restrict__ Pu,
    const float* __restrict__ Qv, const float* __restrict__ Ql, const float* __restrict__ Qu,
    float* __restrict__ Ov, float* __restrict__ Oc, float* __restrict__ Or)
{
    __shared__ float sPv[16][68], sPl[16][68], sPu[16][68];
    __shared__ float sVv[16][64], sVl[16][64], sVu[16][64];
    const int tid = threadIdx.x;
    const int tx = tid & 15, ty = tid >> 4;
    const int bh = blockIdx.z;
    const int b = bh >> 4, h = bh & 15;
    const int m0 = blockIdx.y * 64;
    const int vcol = 2 * EE + h * DHEAD;
    size_t pbase = (size_t)bh * SSEQ * SSEQ;

    float accv[4][4] = {}, accl[4][4] = {}, accu[4][4] = {};

    for (int k0 = 0; k0 < SSEQ; k0 += 16) {
        #pragma unroll
        for (int t = 0; t < 4; t++) {
            int e = tid + t * 256;
            int r = e >> 4, c = e & 15;
            size_t gip = pbase + (size_t)(m0 + r) * SSEQ + k0 + c;
            sPv[c][r] = Pv[gip];
            sPl[c][r] = Pl[gip];
            sPu[c][r] = Pu[gip];
        }
        #pragma unroll
        for (int t = 0; t < 4; t++) {
            int e = tid + t * 256;
            int r = e >> 6, c = e & 63;
            size_t gi = (size_t)(b * SSEQ + k0 + r) * E3 + vcol + c;
            sVv[r][c] = Qv[gi];
            sVl[r][c] = Ql[gi];
            sVu[r][c] = Qu[gi];
        }
        __syncthreads();
        #pragma unroll
        for (int kk = 0; kk < 16; kk++) {
            float pv[4], pl[4], pu[4];
            ld4(pv, &sPv[kk][ty * 4]);
            ld4(pl, &sPl[kk][ty * 4]);
            ld4(pu, &sPu[kk][ty * 4]);
            float bv[4], bl[4], bu[4];
            ld4(bv, &sVv[kk][tx * 4]);
            ld4(bl, &sVl[kk][tx * 4]);
            ld4(bu, &sVu[kk][tx * 4]);
            #pragma unroll
            for (int j = 0; j < 4; j++) {
                bool lp = (bl[j] >= 0.0f);
                bool up = (bu[j] >= 0.0f);
                #pragma unroll
                for (int i = 0; i < 4; i++) {
                    accv[i][j] = fmaf(pv[i], bv[j], accv[i][j]);
                    accl[i][j] = fmaf(lp ? pl[i] : pu[i], bl[j], accl[i][j]);
                    accu[i][j] = fmaf(up ? pu[i] : pl[i], bu[j], accu[i][j]);
                }
            }
        }
        __syncthreads();
    }
    #pragma unroll
    for (int i = 0; i < 4; i++) {
        int m = m0 + ty * 4 + i;
        #pragma unroll
        for (int j = 0; j < 4; j++) {
            int d = tx * 4 + j;
            size_t idx = (size_t)(b * SSEQ + m) * EE + h * DHEAD + d;
            Ov[idx] = accv[i][j];
            Oc[idx] = 0.5f * (accl[i][j] + accu[i][j]);
            Or[idx] = 0.5f * (accu[i][j] - accl[i][j]);
        }
    }
}

// ============================================================================
// Launch
// ============================================================================
extern "C" void kernel_launch(void* const* d_in, const int* in_sizes, int n_in,
                              void* d_out, int out_size) {
    const float* xv = (const float*)d_in[0];
    const float* xl = (const float*)d_in[1];
    const float* xu = (const float*)d_in[2];
    const float* Wi = (const float*)d_in[3];
    const float* bi = (const float*)d_in[4];
    const float* Wo = (const float*)d_in[5];
    const float* bo = (const float*)d_in[6];
    float* out = (float*)d_out;

    float *qv, *ql, *qu, *sv, *sl, *su, *ov, *oc, *orr;
    cudaGetSymbolAddress((void**)&qv, g_qkv_v);
    cudaGetSymbolAddress((void**)&ql, g_qkv_l);
    cudaGetSymbolAddress((void**)&qu, g_qkv_u);
    cudaGetSymbolAddress((void**)&sv, g_s_v);
    cudaGetSymbolAddress((void**)&sl, g_s_l);
    cudaGetSymbolAddress((void**)&su, g_s_u);
    cudaGetSymbolAddress((void**)&ov, g_o_v);
    cudaGetSymbolAddress((void**)&oc, g_o_c);
    cudaGetSymbolAddress((void**)&orr, g_o_r);

    dim3 blk(256);

    // K1: qkv = ibp_linear(x, in_proj) via center-radius (convert l,u on load)
    ibp_linear_cr<true><<<dim3(E3 / 64, MROWS / 64), blk>>>(
        xv, xl, xu, Wi, bi, qv, ql, qu, MROWS, E3, EE);

    // K2: interval scores per (b,h)
    ibp_scores_kernel<<<dim3(SSEQ / 64, SSEQ / 64, NBH), blk>>>(
        qv, ql, qu, sv, sl, su);

    // K3: IBP softmax in-place
    ibp_softmax_kernel<<<(NBH * SSEQ) / 8, blk>>>(sv, sl, su);

    // K4: O = P @ V, outputs val + (center, radius)
    ibp_pv_kernel<<<dim3(1, SSEQ / 64, NBH), blk>>>(
        sv, sl, su, qv, ql, qu, ov, oc, orr);

    // K5: y = ibp_linear(O, out_proj) via center-radius (already c,r)
    ibp_linear_cr<false><<<dim3(EE / 64, MROWS / 64), blk>>>(
        ov, oc, orr, Wo, bo,
        out, out + (size_t)MROWS * EE, out + 2 * (size_t)MROWS * EE,
        MROWS, EE, EE);
}

// round 4
// speedup vs baseline: 2.4124x; 1.4009x over previous
#include <cuda_runtime.h>
#include <cuda_bf16.h>
#include <math.h>
#include <stdint.h>

// Problem constants: B=4, S=512, E=1024, H=16, DH=64
#define MROWS 2048
#define E3    3072
#define EE    1024
#define SSEQ  512
#define NHEAD 16
#define DHEAD 64
#define NBH   64
#define SCALE 0.125f

// ---------------- scratch (device globals) -------------
__device__ float g_qkv_v[(size_t)MROWS * E3];
__device__ float g_qkv_l[(size_t)MROWS * E3];
__device__ float g_qkv_u[(size_t)MROWS * E3];
__device__ float g_s_v[(size_t)NBH * SSEQ * SSEQ];
__device__ float g_s_l[(size_t)NBH * SSEQ * SSEQ];
__device__ float g_s_u[(size_t)NBH * SSEQ * SSEQ];
// bf16 split A operands: (v_hi, v_lo, c_hi, c_lo, r_hi, r_lo), each [MROWS, 1024]
__device__ __nv_bfloat16 g_x6[(size_t)6 * MROWS * EE];
__device__ __nv_bfloat16 g_o6[(size_t)6 * MROWS * EE];
// bf16 split transposed weights [N,K]: (w_hi, w_lo, |w|_hi, |w|_lo)
__device__ __nv_bfloat16 g_wi4[(size_t)4 * E3 * EE];
__device__ __nv_bfloat16 g_wo4[(size_t)4 * EE * EE];

// ============================================================================
// helpers
// ============================================================================
__device__ __forceinline__ uint32_t smem_u32(const void* p) {
    uint32_t a;
    asm("{ .reg .u64 t; cvta.to.shared.u64 t, %1; cvt.u32.u64 %0, t; }" : "=r"(a) : "l"(p));
    return a;
}
__device__ __forceinline__ void cp16(uint32_t dst, const void* src) {
    asm volatile("cp.async.cg.shared.global [%0], [%1], 16;" :: "r"(dst), "l"(src));
}
__device__ __forceinline__ void cp_commit() {
    asm volatile("cp.async.commit_group;" ::: "memory");
}
template<int N>
__device__ __forceinline__ void cp_wait() {
    asm volatile("cp.async.wait_group %0;" :: "n"(N) : "memory");
}
__device__ __forceinline__ void ldsm4(uint32_t addr, uint32_t* r) {
    asm volatile("ldmatrix.sync.aligned.m8n8.x4.shared.b16 {%0,%1,%2,%3}, [%4];"
                 : "=r"(r[0]), "=r"(r[1]), "=r"(r[2]), "=r"(r[3]) : "r"(addr));
}
__device__ __forceinline__ void mma16816(float* d, const uint32_t* a, const uint32_t* b) {
    asm volatile("mma.sync.aligned.m16n8k16.row.col.f32.bf16.bf16.f32 "
        "{%0,%1,%2,%3}, {%4,%5,%6,%7}, {%8,%9}, {%0,%1,%2,%3};"
        : "+f"(d[0]), "+f"(d[1]), "+f"(d[2]), "+f"(d[3])
        : "r"(a[0]), "r"(a[1]), "r"(a[2]), "r"(a[3]), "r"(b[0]), "r"(b[1]));
}
__device__ __forceinline__ void ld4(float* d, const float* s) {
    float4 t = *(const float4*)s;
    d[0] = t.x; d[1] = t.y; d[2] = t.z; d[3] = t.w;
}
__device__ __forceinline__ void split_bf16(float x, __nv_bfloat16& hi, __nv_bfloat16& lo) {
    hi = __float2bfloat16(x);
    lo = __float2bfloat16(x - __bfloat162float(hi));
}

// ============================================================================
// prep_x: x(v,l,u) -> 6 bf16 split arrays (v,c,r hi/lo), [M,K] row-major
// ============================================================================
__global__ void prep_x_kernel(const float* __restrict__ xv, const float* __restrict__ xl,
                              const float* __restrict__ xu, __nv_bfloat16* __restrict__ o)
{
    size_t i = (size_t)blockIdx.x * 256 + threadIdx.x;
    const size_t S = (size_t)MROWS * EE;
    float v = xv[i], l = xl[i], u = xu[i];
    float c = 0.5f * (l + u), r = 0.5f * (u - l);
    __nv_bfloat16 hi, lo;
    split_bf16(v, hi, lo); o[i] = hi;         o[S + i] = lo;
    split_bf16(c, hi, lo); o[2 * S + i] = hi; o[3 * S + i] = lo;
    split_bf16(r, hi, lo); o[4 * S + i] = hi; o[5 * S + i] = lo;
}

// ============================================================================
// prep_w: W [K,N] -> transposed bf16 splits [N,K]: (w_hi, w_lo, |w|_hi, |w|_lo)
// ============================================================================
__global__ void prep_w_kernel(const float* __restrict__ W, __nv_bfloat16* __restrict__ o,
                              int K, int N)
{
    __shared__ float tile[32][33];
    const int n0 = blockIdx.x * 32, k0 = blockIdx.y * 32;
    const int tx = threadIdx.x & 31, ty = threadIdx.x >> 5;
    const size_t S = (size_t)K * N;
    #pragma unroll
    for (int i = 0; i < 32; i += 8)
        tile[ty + i][tx] = W[(size_t)(k0 + ty + i) * N + n0 + tx];
    __syncthreads();
    #pragma unroll
    for (int i = 0; i < 32; i += 8) {
        float w = tile[tx][ty + i];
        size_t oi = (size_t)(n0 + ty + i) * K + k0 + tx;
        __nv_bfloat16 hi, lo;
        split_bf16(w, hi, lo);
        o[oi] = hi; o[S + oi] = lo;
        split_bf16(fabsf(w), hi, lo);
        o[2 * S + oi] = hi; o[3 * S + oi] = lo;
    }
}

// ============================================================================
// mma.sync IBP linear (bf16-split, exact-CR):
//   val = v@W + b ; c' = c@W ; r' = r@|W| ; Yl = c'-r'+b ; Yu = c'+r'+b
// Each product via 3 bf16 MMAs (hi*hi + hi*lo + lo*hi).
// CTA 128x64, 8 warps (4M x 2N), warp tile 32x32, BK=32, double-buffered.
// ============================================================================
#define BM 128
#define BN 64
#define BK 32
#define APITCH 80                     /* 64B row + 16B pad: conflict-free ldsm */
#define A_CH_BYTES (BM * APITCH)      /* 10240 */
#define B_CH_BYTES (BN * APITCH)      /* 5120  */
#define A_BYTES (6 * A_CH_BYTES)      /* 61440 */
#define B_BYTES (4 * B_CH_BYTES)      /* 20480 */
#define STAGE_BYTES (A_BYTES + B_BYTES) /* 81920 */
#define GEMM_SMEM (2 * STAGE_BYTES)     /* 163840 */

__global__ void __launch_bounds__(256, 1) ibp_gemm_mma(
    const __nv_bfloat16* __restrict__ A6,   // 6 channels, each [MROWS, K]
    const __nv_bfloat16* __restrict__ B4,   // 4 channels, each [Nmat, K]
    const float* __restrict__ bias,
    float* __restrict__ Yv, float* __restrict__ Yl, float* __restrict__ Yu,
    int K, int Nmat)
{
    extern __shared__ char smem[];
    const uint32_t sbase = smem_u32(smem);
    const int tid = threadIdx.x;
    const int warp = tid >> 5, lane = tid & 31;
    const int wm = warp >> 1, wn = warp & 1;
    const int m0 = blockIdx.y * BM, n0 = blockIdx.x * BN;
    const size_t aStride = (size_t)MROWS * K;
    const size_t bStride = (size_t)Nmat * K;

    float acc[3][2][4][4];
    #pragma unroll
    for (int cc = 0; cc < 3; cc++)
        #pragma unroll
        for (int f = 0; f < 2; f++)
            #pragma unroll
            for (int g = 0; g < 4; g++)
                #pragma unroll
                for (int q = 0; q < 4; q++) acc[cc][f][g][q] = 0.0f;

    auto load_stage = [&](int stage, int k0) {
        const uint32_t sa = sbase + stage * STAGE_BYTES;
        #pragma unroll
        for (int t = 0; t < 12; t++) {               // A: 3072 x 16B
            int u = tid + t * 256;
            int ch = u >> 9, rem = u & 511, row = rem >> 2, c4 = rem & 3;
            uint32_t dst = sa + ch * A_CH_BYTES + row * APITCH + c4 * 16;
            const char* src = (const char*)(A6 + (size_t)ch * aStride
                              + (size_t)(m0 + row) * K + k0) + c4 * 16;
            cp16(dst, src);
        }
        #pragma unroll
        for (int t = 0; t < 4; t++) {                // B: 1024 x 16B
            int u = tid + t * 256;
            int ch = u >> 8, rem = u & 255, row = rem >> 2, c4 = rem & 3;
            uint32_t dst = sa + A_BYTES + ch * B_CH_BYTES + row * APITCH + c4 * 16;
            const char* src = (const char*)(B4 + (size_t)ch * bStride
                              + (size_t)(n0 + row) * K + k0) + c4 * 16;
            cp16(dst, src);
        }
        cp_commit();
    };

    const int KT = K / BK;
    load_stage(0, 0);

    // ldmatrix lane address components
    const int arow = lane & 15;                      // A: row within m16 frag
    const int aksel = (lane >> 4) * 16;              // A: k-half select (bytes)
    const int brow = ((lane >> 4) & 1) * 8 + (lane & 7);   // B: n within n16
    const int bksel = ((lane >> 3) & 1) * 16;        // B: k-half select (bytes)

    for (int kt = 0; kt < KT; kt++) {
        if (kt + 1 < KT) { load_stage((kt + 1) & 1, (kt + 1) * BK); cp_wait<1>(); }
        else             { cp_wait<0>(); }
        __syncthreads();
        const uint32_t sa = sbase + (kt & 1) * STAGE_BYTES;

        #pragma unroll
        for (int s = 0; s < 2; s++) {                // two k16 steps in BK=32
            // B fragments: 4 channels x 4 n8-frags x 2 regs
            uint32_t bf[4][4][2];
            #pragma unroll
            for (int ch = 0; ch < 4; ch++) {
                #pragma unroll
                for (int pr = 0; pr < 2; pr++) {
                    uint32_t r[4];
                    uint32_t addr = sa + A_BYTES + ch * B_CH_BYTES
                                  + (wn * 32 + pr * 16 + brow) * APITCH
                                  + s * 32 + bksel;
                    ldsm4(addr, r);
                    bf[ch][pr * 2 + 0][0] = r[0]; bf[ch][pr * 2 + 0][1] = r[1];
                    bf[ch][pr * 2 + 1][0] = r[2]; bf[ch][pr * 2 + 1][1] = r[3];
                }
            }
            #pragma unroll
            for (int cc = 0; cc < 3; cc++) {         // channel classes v, c, r
                uint32_t af[2][2][4];                // [hi/lo][mfrag][4]
                #pragma unroll
                for (int p = 0; p < 2; p++) {
                    int ch = cc * 2 + p;
                    #pragma unroll
                    for (int f = 0; f < 2; f++) {
                        uint32_t addr = sa + ch * A_CH_BYTES
                                      + (wm * 32 + f * 16 + arow) * APITCH
                                      + s * 32 + aksel;
                        ldsm4(addr, af[p][f]);
                    }
                }
                const int bch = (cc == 2) ? 2 : 0;   // r-channel uses |W| tiles
                #pragma unroll
                for (int f = 0; f < 2; f++) {
                    #pragma unroll
                    for (int g = 0; g < 4; g++) {
                        mma16816(acc[cc][f][g], af[0][f], bf[bch][g]);      // hi*hi
                        mma16816(acc[cc][f][g], af[0][f], bf[bch + 1][g]); // hi*lo
                        mma16816(acc[cc][f][g], af[1][f], bf[bch][g]);     // lo*hi
                    }
                }
            }
        }
        __syncthreads();
    }

    // ---- epilogue: registers -> global directly ----
    const int colBase = n0 + wn * 32 + (lane & 3) * 2;
    const int rowBase = m0 + wm * 32 + (lane >> 2);
    #pragma unroll
    for (int f = 0; f < 2; f++) {
        #pragma unroll
        for (int g = 0; g < 4; g++) {
            int col = colBase + g * 8;
            float2 bb = *(const float2*)(bias + col);
            #pragma unroll
            for (int half = 0; half < 2; half++) {
                int row = rowBase + f * 16 + half * 8;
                size_t gi = (size_t)row * Nmat + col;
                int d = half * 2;
                float v0 = acc[0][f][g][d],     v1 = acc[0][f][g][d + 1];
                float c0 = acc[1][f][g][d],     c1 = acc[1][f][g][d + 1];
                float r0 = acc[2][f][g][d],     r1 = acc[2][f][g][d + 1];
                *(float2*)(Yv + gi) = make_float2(v0 + bb.x, v1 + bb.y);
                *(float2*)(Yl + gi) = make_float2(c0 - r0 + bb.x, c1 - r1 + bb.y);
                *(float2*)(Yu + gi) = make_float2(c0 + r0 + bb.x, c1 + r1 + bb.y);
            }
        }
    }
}

// ============================================================================
// K2: interval scores  S = (q*SCALE) @ k^T  (exact sign-select form, SIMT)
// ============================================================================
__global__ void __launch_bounds__(256, 2) ibp_scores_kernel(
    const float* __restrict__ Qv, const float* __restrict__ Ql, const float* __restrict__ Qu,
    float* __restrict__ Sv, float* __restrict__ Sl, float* __restrict__ Su)
{
    __shared__ float sAv[16][68], sAl[16][68], sAu[16][68];
    __shared__ float sBv[16][68], sBl[16][68], sBu[16][68];
    const int tid = threadIdx.x;
    const int tx = tid & 15, ty = tid >> 4;
    const int bh = blockIdx.z;
    const int b = bh >> 4, h = bh & 15;
    const int m0 = blockIdx.y * 64, n0 = blockIdx.x * 64;
    const int qcol = h * DHEAD;
    const int kcol = EE + h * DHEAD;

    float accv[4][4] = {}, accl[4][4] = {}, accu[4][4] = {};

    for (int k0 = 0; k0 < DHEAD; k0 += 16) {
        #pragma unroll
        for (int t = 0; t < 4; t++) {
            int e = tid + t * 256;
            int r = e >> 4, c = e & 15;
            size_t gia = (size_t)(b * SSEQ + m0 + r) * E3 + qcol + k0 + c;
            sAv[c][r] = Qv[gia] * SCALE;
            sAl[c][r] = Ql[gia] * SCALE;
            sAu[c][r] = Qu[gia] * SCALE;
            size_t gib = (size_t)(b * SSEQ + n0 + r) * E3 + kcol + k0 + c;
            sBv[c][r] = Qv[gib];
            sBl[c][r] = Ql[gib];
            sBu[c][r] = Qu[gib];
        }
        __syncthreads();
        #pragma unroll
        for (int kk = 0; kk < 16; kk++) {
            float av[4], al4[4], au4[4];
            float pal[4], nal[4], pau[4], nau[4];
            ld4(av, &sAv[kk][ty * 4]);
            ld4(al4, &sAl[kk][ty * 4]);
            ld4(au4, &sAu[kk][ty * 4]);
            #pragma unroll
            for (int i = 0; i < 4; i++) {
                pal[i] = fmaxf(al4[i], 0.0f); nal[i] = fminf(al4[i], 0.0f);
                pau[i] = fmaxf(au4[i], 0.0f); nau[i] = fminf(au4[i], 0.0f);
            }
            float bv[4], bl[4], bu[4];
            ld4(bv, &sBv[kk][tx * 4]);
            ld4(bl, &sBl[kk][tx * 4]);
            ld4(bu, &sBu[kk][tx * 4]);
            #pragma unroll
            for (int j = 0; j < 4; j++) {
                bool lp = (bl[j] >= 0.0f);
                bool up = (bu[j] >= 0.0f);
                #pragma unroll
                for (int i = 0; i < 4; i++) {
                    accv[i][j] = fmaf(av[i], bv[j], accv[i][j]);
                    float cl = lp ? pal[i] : pau[i];
                    float cu = up ? nal[i] : nau[i];
                    accl[i][j] = fmaf(cl, bl[j], fmaf(cu, bu[j], accl[i][j]));
                    float dl = up ? pau[i] : pal[i];
                    float du = lp ? nau[i] : nal[i];
                    accu[i][j] = fmaf(dl, bu[j], fmaf(du, bl[j], accu[i][j]));
                }
            }
        }
        __syncthreads();
    }
    #pragma unroll
    for (int i = 0; i < 4; i++) {
        int m = m0 + ty * 4 + i;
        #pragma unroll
        for (int j = 0; j < 4; j++) {
            int n = n0 + tx * 4 + j;
            size_t idx = ((size_t)bh * SSEQ + m) * SSEQ + n;
            Sv[idx] = accv[i][j];
            Sl[idx] = accl[i][j];
            Su[idx] = accu[i][j];
        }
    }
}

// ============================================================================
// K3: IBP softmax, in-place; emits (pv, pc, pr): pc=(pl+pu)/2, pr=(pu-pl)/2
// ============================================================================
__global__ void __launch_bounds__(256) ibp_softmax_kernel(
    float* __restrict__ Sv, float* __restrict__ Sl, float* __restrict__ Su)
{
    const int row  = blockIdx.x * 8 + (threadIdx.x >> 5);
    const int lane = threadIdx.x & 31;
    size_t base = (size_t)row * SSEQ + lane;

    float v[16], l[16], u[16];
    #pragma unroll
    for (int t = 0; t < 16; t++) {
        v[t] = Sv[base + t * 32];
        l[t] = Sl[base + t * 32];
        u[t] = Su[base + t * 32];
    }
    float mu = -INFINITY, mv = -INFINITY;
    #pragma unroll
    for (int t = 0; t < 16; t++) { mu = fmaxf(mu, u[t]); mv = fmaxf(mv, v[t]); }
    #pragma unroll
    for (int o = 16; o > 0; o >>= 1) {
        mu = fmaxf(mu, __shfl_xor_sync(0xFFFFFFFFu, mu, o));
        mv = fmaxf(mv, __shfl_xor_sync(0xFFFFFFFFu, mv, o));
    }
    float sumv = 0.0f, suml = 0.0f, sumu = 0.0f;
    #pragma unroll
    for (int t = 0; t < 16; t++) {
        v[t] = __expf(v[t] - mv);
        l[t] = __expf(l[t] - mu);
        u[t] = __expf(u[t] - mu);
        sumv += v[t]; suml += l[t]; sumu += u[t];
    }
    #pragma unroll
    for (int o = 16; o > 0; o >>= 1) {
        sumv += __shfl_xor_sync(0xFFFFFFFFu, sumv, o);
        suml += __shfl_xor_sync(0xFFFFFFFFu, suml, o);
        sumu += __shfl_xor_sync(0xFFFFFFFFu, sumu, o);
    }
    #pragma unroll
    for (int t = 0; t < 16; t++) {
        float pv = v[t] / sumv;
        float pl = l[t] / (sumu - u[t] + l[t]);
        float pu = u[t] / (suml - l[t] + u[t]);
        pl = fminf(fmaxf(pl, 0.0f), 1.0f);
        pu = fminf(fmaxf(pu, 0.0f), 1.0f);
        Sv[base + t * 32] = pv;
        Sl[base + t * 32] = 0.5f * (pl + pu);   // pc
        Su[base + t * 32] = 0.5f * (pu - pl);   // pr
    }
}

// ============================================================================
// K4: O = P @ V; select-free CR form (exact for P>=0):
//   lb += pc*vl - pr*|vl|,  ub += pc*vu + pr*|vu|
// Epilogue writes bf16-split (v,c,r hi/lo) arrays for K5 directly.
// ============================================================================
__global__ void __launch_bounds__(256, 2) ibp_pv_kernel(
    const float* __restrict__ Pv, const float* __restrict__ Pc, const float* __restrict__ Pr,
    const float* __restrict__ Qv, const float* __restrict__ Ql, const float* __restrict__ Qu,
    __nv_bfloat16* __restrict__ O6)
{
    __shared__ float sPv[16][68], sPc[16][68], sPr[16][68];
    __shared__ float sVv[16][64], sVl[16][64], sVu[16][64];
    const int tid = threadIdx.x;
    const int tx = tid & 15, ty = tid >> 4;
    const int bh = blockIdx.z;
    const int b = bh >> 4, h = bh & 15;
    const int m0 = blockIdx.y * 64;
    const int vcol = 2 * EE + h * DHEAD;
    size_t pbase = (size_t)bh * SSEQ * SSEQ;
    const size_t OS = (size_t)MROWS * EE;

    float accv[4][4] = {}, accl[4][4] = {}, accu[4][4] = {};

    for (int k0 = 0; k0 < SSEQ; k0 += 16) {
        #pragma unroll
        for (int t = 0; t < 4; t++) {
            int e = tid + t * 256;
            int r = e >> 4, c = e & 15;
            size_t gip = pbase + (size_t)(m0 + r) * SSEQ + k0 + c;
            sPv[c][r] = Pv[gip];
            sPc[c][r] = Pc[gip];
            sPr[c][r] = Pr[gip];
        }
        #pragma unroll
        for (int t = 0; t < 4; t++) {
            int e = tid + t * 256;
            int r = e >> 6, c = e & 63;
            size_t gi = (size_t)(b * SSEQ + k0 + r) * E3 + vcol + c;
            sVv[r][c] = Qv[gi];
            sVl[r][c] = Ql[gi];
            sVu[r][c] = Qu[gi];
        }
        __syncthreads();
        #pragma unroll
        for (int kk = 0; kk < 16; kk++) {
            float pv[4], pc[4], pr[4];
            ld4(pv, &sPv[kk][ty * 4]);
            ld4(pc, &sPc[kk][ty * 4]);
            ld4(pr, &sPr[kk][ty * 4]);
            float bv[4], bl[4], bu[4];
            ld4(bv, &sVv[kk][tx * 4]);
            ld4(bl, &sVl[kk][tx * 4]);
            ld4(bu, &sVu[kk][tx * 4]);
            #pragma unroll
            for (int j = 0; j < 4; j++) {
                float abl = fabsf(bl[j]);
                float abu = fabsf(bu[j]);
                #pragma unroll
                for (int i = 0; i < 4; i++) {
                    accv[i][j] = fmaf(pv[i], bv[j], accv[i][j]);
                    accl[i][j] = fmaf(pc[i], bl[j], accl[i][j]);
                    accl[i][j] = fmaf(pr[i], -abl, accl[i][j]);
                    accu[i][j] = fmaf(pc[i], bu[j], accu[i][j]);
                    accu[i][j] = fmaf(pr[i], abu, accu[i][j]);
                }
            }
        }
        __syncthreads();
    }
    #pragma unroll
    for (int i = 0; i < 4; i++) {
        int m = m0 + ty * 4 + i;
        #pragma unroll
        for (int j = 0; j < 4; j++) {
            int d = tx * 4 + j;
            size_t idx = (size_t)(b * SSEQ + m) * EE + h * DHEAD + d;
            float v = accv[i][j];
            float c = 0.5f * (accl[i][j] + accu[i][j]);
            float r = 0.5f * (accu[i][j] - accl[i][j]);
            __nv_bfloat16 hi, lo;
            split_bf16(v, hi, lo); O6[idx] = hi;          O6[OS + idx] = lo;
            split_bf16(c, hi, lo); O6[2 * OS + idx] = hi; O6[3 * OS + idx] = lo;
            split_bf16(r, hi, lo); O6[4 * OS + idx] = hi; O6[5 * OS + idx] = lo;
        }
    }
}

// ============================================================================
// Launch
// ============================================================================
extern "C" void kernel_launch(void* const* d_in, const int* in_sizes, int n_in,
                              void* d_out, int out_size) {
    const float* xv = (const float*)d_in[0];
    const float* xl = (const float*)d_in[1];
    const float* xu = (const float*)d_in[2];
    const float* Wi = (const float*)d_in[3];
    const float* bi = (const float*)d_in[4];
    const float* Wo = (const float*)d_in[5];
    const float* bo = (const float*)d_in[6];
    float* out = (float*)d_out;

    float *qv, *ql, *qu, *sv, *sl, *su;
    __nv_bfloat16 *x6, *o6, *wi4, *wo4;
    cudaGetSymbolAddress((void**)&qv, g_qkv_v);
    cudaGetSymbolAddress((void**)&ql, g_qkv_l);
    cudaGetSymbolAddress((void**)&qu, g_qkv_u);
    cudaGetSymbolAddress((void**)&sv, g_s_v);
    cudaGetSymbolAddress((void**)&sl, g_s_l);
    cudaGetSymbolAddress((void**)&su, g_s_u);
    cudaGetSymbolAddress((void**)&x6, g_x6);
    cudaGetSymbolAddress((void**)&o6, g_o6);
    cudaGetSymbolAddress((void**)&wi4, g_wi4);
    cudaGetSymbolAddress((void**)&wo4, g_wo4);

    cudaFuncSetAttribute(ibp_gemm_mma, cudaFuncAttributeMaxDynamicSharedMemorySize, GEMM_SMEM);

    dim3 blk(256);

    // Prep: bf16 splits of x (v,c,r) and transposed weight splits
    prep_x_kernel<<<(MROWS * EE) / 256, blk>>>(xv, xl, xu, x6);
    prep_w_kernel<<<dim3(E3 / 32, EE / 32), blk>>>(Wi, wi4, EE, E3);
    prep_w_kernel<<<dim3(EE / 32, EE / 32), blk>>>(Wo, wo4, EE, EE);

    // K1 (HMMA): qkv = ibp_linear(x, in_proj)
    ibp_gemm_mma<<<dim3(E3 / BN, MROWS / BM), blk, GEMM_SMEM>>>(
        x6, wi4, bi, qv, ql, qu, EE, E3);

    // K2: interval scores per (b,h)
    ibp_scores_kernel<<<dim3(SSEQ / 64, SSEQ / 64, NBH), blk>>>(
        qv, ql, qu, sv, sl, su);

    // K3: IBP softmax in-place (emits pv, pc, pr)
    ibp_softmax_kernel<<<(NBH * SSEQ) / 8, blk>>>(sv, sl, su);

    // K4: O = P @ V, writes bf16 splits for K5
    ibp_pv_kernel<<<dim3(1, SSEQ / 64, NBH), blk>>>(
        sv, sl, su, qv, ql, qu, o6);

    // K5 (HMMA): y = ibp_linear(O, out_proj) -> d_out [3][2048][1024]
    ibp_gemm_mma<<<dim3(EE / BN, MROWS / BM), blk, GEMM_SMEM>>>(
        o6, wo4, bo, out, out + (size_t)MROWS * EE, out + 2 * (size_t)MROWS * EE,
        EE, EE);
}

// round 5
// speedup vs baseline: 3.4488x; 1.4296x over previous
#include <cuda_runtime.h>
#include <cuda_bf16.h>
#include <math.h>
#include <stdint.h>

// Problem constants: B=4, S=512, E=1024, H=16, DH=64
#define MROWS 2048
#define E3    3072
#define EE    1024
#define SSEQ  512
#define NHEAD 16
#define DHEAD 64
#define NBH   64
#define SCALE 0.125f

// ---------------- scratch (device globals) -------------
__device__ float g_qkv_v[(size_t)MROWS * E3];
__device__ float g_qkv_l[(size_t)MROWS * E3];
__device__ float g_qkv_u[(size_t)MROWS * E3];
__device__ float g_s_v[(size_t)NBH * SSEQ * SSEQ];
__device__ float g_s_l[(size_t)NBH * SSEQ * SSEQ];
__device__ float g_s_u[(size_t)NBH * SSEQ * SSEQ];
// bf16 split A operands for big linears
__device__ __nv_bfloat16 g_x6[(size_t)6 * MROWS * EE];
__device__ __nv_bfloat16 g_o6[(size_t)6 * MROWS * EE];
// bf16 split transposed weights [N,K]: (w_hi, w_lo, |w|_hi, |w|_lo)
__device__ __nv_bfloat16 g_wi4[(size_t)4 * E3 * EE];
__device__ __nv_bfloat16 g_wo4[(size_t)4 * EE * EE];
// K2 operands: 10 channels each, layout [ch][bh][s][dh]
// A pairs: 0=qv 1=pos(ql) 2=pos(qu) 3=neg(ql) 4=neg(qu)  (scaled, hi/lo)
// B pairs: 0=kv 1=pos(kl) 2=neg(kl) 3=pos(ku) 4=neg(ku)  (hi/lo)
__device__ __nv_bfloat16 g_qa[(size_t)10 * NBH * SSEQ * DHEAD];
__device__ __nv_bfloat16 g_ka[(size_t)10 * NBH * SSEQ * DHEAD];
// K4 A operand: P splits [ch][bh][sq][sk]: pv,pc,pr (hi/lo)
__device__ __nv_bfloat16 g_p6[(size_t)6 * NBH * SSEQ * SSEQ];
// K4 B operand: V^T splits [ch][bh][dh][sk]: Vv, Vl, -|Vl|, Vu, |Vu| (hi/lo)
__device__ __nv_bfloat16 g_vt[(size_t)10 * NBH * DHEAD * SSEQ];

// ============================================================================
// helpers
// ============================================================================
__device__ __forceinline__ uint32_t smem_u32(const void* p) {
    uint32_t a;
    asm("{ .reg .u64 t; cvta.to.shared.u64 t, %1; cvt.u32.u64 %0, t; }" : "=r"(a) : "l"(p));
    return a;
}
__device__ __forceinline__ void cp16(uint32_t dst, const void* src) {
    asm volatile("cp.async.cg.shared.global [%0], [%1], 16;" :: "r"(dst), "l"(src));
}
__device__ __forceinline__ void cp_commit() {
    asm volatile("cp.async.commit_group;" ::: "memory");
}
template<int N>
__device__ __forceinline__ void cp_wait() {
    asm volatile("cp.async.wait_group %0;" :: "n"(N) : "memory");
}
__device__ __forceinline__ void ldsm4(uint32_t addr, uint32_t* r) {
    asm volatile("ldmatrix.sync.aligned.m8n8.x4.shared.b16 {%0,%1,%2,%3}, [%4];"
                 : "=r"(r[0]), "=r"(r[1]), "=r"(r[2]), "=r"(r[3]) : "r"(addr));
}
__device__ __forceinline__ void mma16816(float* d, const uint32_t* a, const uint32_t* b) {
    asm volatile("mma.sync.aligned.m16n8k16.row.col.f32.bf16.bf16.f32 "
        "{%0,%1,%2,%3}, {%4,%5,%6,%7}, {%8,%9}, {%0,%1,%2,%3};"
        : "+f"(d[0]), "+f"(d[1]), "+f"(d[2]), "+f"(d[3])
        : "r"(a[0]), "r"(a[1]), "r"(a[2]), "r"(a[3]), "r"(b[0]), "r"(b[1]));
}
__device__ __forceinline__ void split_bf16(float x, __nv_bfloat16& hi, __nv_bfloat16& lo) {
    hi = __float2bfloat16(x);
    lo = __float2bfloat16(x - __bfloat162float(hi));
}

// ============================================================================
// prep_x: x(v,l,u) -> 6 bf16 split arrays (v,c,r hi/lo)
// ============================================================================
__global__ void prep_x_kernel(const float* __restrict__ xv, const float* __restrict__ xl,
                              const float* __restrict__ xu, __nv_bfloat16* __restrict__ o)
{
    size_t i = (size_t)blockIdx.x * 256 + threadIdx.x;
    const size_t S = (size_t)MROWS * EE;
    float v = xv[i], l = xl[i], u = xu[i];
    float c = 0.5f * (l + u), r = 0.5f * (u - l);
    __nv_bfloat16 hi, lo;
    split_bf16(v, hi, lo); o[i] = hi;         o[S + i] = lo;
    split_bf16(c, hi, lo); o[2 * S + i] = hi; o[3 * S + i] = lo;
    split_bf16(r, hi, lo); o[4 * S + i] = hi; o[5 * S + i] = lo;
}

// ============================================================================
// prep_w: W [K,N] -> transposed bf16 splits [N,K]: (w_hi, w_lo, |w|_hi, |w|_lo)
// ============================================================================
__global__ void prep_w_kernel(const float* __restrict__ W, __nv_bfloat16* __restrict__ o,
                              int K, int N)
{
    __shared__ float tile[32][33];
    const int n0 = blockIdx.x * 32, k0 = blockIdx.y * 32;
    const int tx = threadIdx.x & 31, ty = threadIdx.x >> 5;
    const size_t S = (size_t)K * N;
    #pragma unroll
    for (int i = 0; i < 32; i += 8)
        tile[ty + i][tx] = W[(size_t)(k0 + ty + i) * N + n0 + tx];
    __syncthreads();
    #pragma unroll
    for (int i = 0; i < 32; i += 8) {
        float w = tile[tx][ty + i];
        size_t oi = (size_t)(n0 + ty + i) * K + k0 + tx;
        __nv_bfloat16 hi, lo;
        split_bf16(w, hi, lo);
        o[oi] = hi; o[S + oi] = lo;
        split_bf16(fabsf(w), hi, lo);
        o[2 * S + oi] = hi; o[3 * S + oi] = lo;
    }
}

// ============================================================================
// prep_qk: qkv fp32 -> per-(b,h) bf16 clamp-split channels for K2
// ============================================================================
__global__ void prep_qk_kernel(const float* __restrict__ Qv, const float* __restrict__ Ql,
                               const float* __restrict__ Qu,
                               __nv_bfloat16* __restrict__ qa, __nv_bfloat16* __restrict__ ka)
{
    size_t i = (size_t)blockIdx.x * 256 + threadIdx.x;  // over NBH*512*64
    const size_t CH = (size_t)NBH * SSEQ * DHEAD;
    int bh = (int)(i >> 15);            // /(512*64)
    int rem = (int)(i & 32767);
    int s = rem >> 6, d = rem & 63;
    int b = bh >> 4, h = bh & 15;
    size_t src = (size_t)(b * SSEQ + s) * E3 + h * DHEAD + d;
    float qv = Qv[src] * SCALE, ql = Ql[src] * SCALE, qu = Qu[src] * SCALE;
    float kv = Qv[src + EE], kl = Ql[src + EE], ku = Qu[src + EE];
    __nv_bfloat16 hi, lo;
    split_bf16(qv, hi, lo);             qa[i] = hi;          qa[CH + i] = lo;
    split_bf16(fmaxf(ql, 0.f), hi, lo); qa[2 * CH + i] = hi; qa[3 * CH + i] = lo;
    split_bf16(fmaxf(qu, 0.f), hi, lo); qa[4 * CH + i] = hi; qa[5 * CH + i] = lo;
    split_bf16(fminf(ql, 0.f), hi, lo); qa[6 * CH + i] = hi; qa[7 * CH + i] = lo;
    split_bf16(fminf(qu, 0.f), hi, lo); qa[8 * CH + i] = hi; qa[9 * CH + i] = lo;
    split_bf16(kv, hi, lo);             ka[i] = hi;          ka[CH + i] = lo;
    split_bf16(fmaxf(kl, 0.f), hi, lo); ka[2 * CH + i] = hi; ka[3 * CH + i] = lo;
    split_bf16(fminf(kl, 0.f), hi, lo); ka[4 * CH + i] = hi; ka[5 * CH + i] = lo;
    split_bf16(fmaxf(ku, 0.f), hi, lo); ka[6 * CH + i] = hi; ka[7 * CH + i] = lo;
    split_bf16(fminf(ku, 0.f), hi, lo); ka[8 * CH + i] = hi; ka[9 * CH + i] = lo;
}

// ============================================================================
// prep_vt: V channels transposed per (b,h): [dh][s] splits for K4 B operand
// ============================================================================
__global__ void prep_vt_kernel(const float* __restrict__ Qv, const float* __restrict__ Ql,
                               const float* __restrict__ Qu, __nv_bfloat16* __restrict__ vt)
{
    __shared__ float tv[32][33], tl[32][33], tu[32][33];
    const int bh = blockIdx.z, b = bh >> 4, h = bh & 15;
    const int s0 = blockIdx.x * 32, d0 = blockIdx.y * 32;
    const int tx = threadIdx.x & 31, ty = threadIdx.x >> 5;
    const size_t CHV = (size_t)NBH * DHEAD * SSEQ;
    #pragma unroll
    for (int i = 0; i < 32; i += 8) {
        size_t src = (size_t)(b * SSEQ + s0 + ty + i) * E3 + 2 * EE + h * DHEAD + d0 + tx;
        tv[ty + i][tx] = Qv[src];
        tl[ty + i][tx] = Ql[src];
        tu[ty + i][tx] = Qu[src];
    }
    __syncthreads();
    #pragma unroll
    for (int i = 0; i < 32; i += 8) {
        int d = d0 + ty + i, s = s0 + tx;
        float v = tv[tx][ty + i], l = tl[tx][ty + i], u = tu[tx][ty + i];
        size_t dst = (size_t)bh * DHEAD * SSEQ + (size_t)d * SSEQ + s;
        __nv_bfloat16 hi, lo;
        split_bf16(v, hi, lo);          vt[dst] = hi;           vt[CHV + dst] = lo;
        split_bf16(l, hi, lo);          vt[2 * CHV + dst] = hi; vt[3 * CHV + dst] = lo;
        split_bf16(-fabsf(l), hi, lo);  vt[4 * CHV + dst] = hi; vt[5 * CHV + dst] = lo;
        split_bf16(u, hi, lo);          vt[6 * CHV + dst] = hi; vt[7 * CHV + dst] = lo;
        split_bf16(fabsf(u), hi, lo);   vt[8 * CHV + dst] = hi; vt[9 * CHV + dst] = lo;
    }
}

// ============================================================================
// mma.sync IBP linear (bf16-split, exact-CR). Interleaved split terms.
// CTA 128x64, 8 warps (4M x 2N), warp tile 32x32, BK=32, double-buffered.
// ============================================================================
#define BM 128
#define BN 64
#define BK 32
#define APITCH 80
#define A_CH_BYTES (BM * APITCH)
#define B_CH_BYTES (BN * APITCH)
#define A_BYTES (6 * A_CH_BYTES)
#define B_BYTES (4 * B_CH_BYTES)
#define STAGE_BYTES (A_BYTES + B_BYTES)
#define GEMM_SMEM (2 * STAGE_BYTES)

__global__ void __launch_bounds__(256, 1) ibp_gemm_mma(
    const __nv_bfloat16* __restrict__ A6,
    const __nv_bfloat16* __restrict__ B4,
    const float* __restrict__ bias,
    float* __restrict__ Yv, float* __restrict__ Yl, float* __restrict__ Yu,
    int K, int Nmat)
{
    extern __shared__ char smem[];
    const uint32_t sbase = smem_u32(smem);
    const int tid = threadIdx.x;
    const int warp = tid >> 5, lane = tid & 31;
    const int wm = warp >> 1, wn = warp & 1;
    const int m0 = blockIdx.y * BM, n0 = blockIdx.x * BN;
    const size_t aStride = (size_t)MROWS * K;
    const size_t bStride = (size_t)Nmat * K;

    float acc[3][2][4][4];
    #pragma unroll
    for (int cc = 0; cc < 3; cc++)
        #pragma unroll
        for (int f = 0; f < 2; f++)
            #pragma unroll
            for (int g = 0; g < 4; g++)
                #pragma unroll
                for (int q = 0; q < 4; q++) acc[cc][f][g][q] = 0.0f;

    auto load_stage = [&](int stage, int k0) {
        const uint32_t sa = sbase + stage * STAGE_BYTES;
        #pragma unroll
        for (int t = 0; t < 12; t++) {
            int u = tid + t * 256;
            int ch = u >> 9, rem = u & 511, row = rem >> 2, c4 = rem & 3;
            cp16(sa + ch * A_CH_BYTES + row * APITCH + c4 * 16,
                 (const char*)(A6 + (size_t)ch * aStride + (size_t)(m0 + row) * K + k0) + c4 * 16);
        }
        #pragma unroll
        for (int t = 0; t < 4; t++) {
            int u = tid + t * 256;
            int ch = u >> 8, rem = u & 255, row = rem >> 2, c4 = rem & 3;
            cp16(sa + A_BYTES + ch * B_CH_BYTES + row * APITCH + c4 * 16,
                 (const char*)(B4 + (size_t)ch * bStride + (size_t)(n0 + row) * K + k0) + c4 * 16);
        }
        cp_commit();
    };

    const int KT = K / BK;
    load_stage(0, 0);

    const int arow = lane & 15;
    const int aksel = (lane >> 4) * 16;
    const int brow = ((lane >> 4) & 1) * 8 + (lane & 7);
    const int bksel = ((lane >> 3) & 1) * 16;

    for (int kt = 0; kt < KT; kt++) {
        if (kt + 1 < KT) { load_stage((kt + 1) & 1, (kt + 1) * BK); cp_wait<1>(); }
        else             { cp_wait<0>(); }
        __syncthreads();
        const uint32_t sa = sbase + (kt & 1) * STAGE_BYTES;

        #pragma unroll
        for (int s = 0; s < 2; s++) {
            uint32_t bf[4][4][2];
            #pragma unroll
            for (int ch = 0; ch < 4; ch++) {
                #pragma unroll
                for (int pr = 0; pr < 2; pr++) {
                    uint32_t r[4];
                    ldsm4(sa + A_BYTES + ch * B_CH_BYTES
                          + (wn * 32 + pr * 16 + brow) * APITCH + s * 32 + bksel, r);
                    bf[ch][pr * 2 + 0][0] = r[0]; bf[ch][pr * 2 + 0][1] = r[1];
                    bf[ch][pr * 2 + 1][0] = r[2]; bf[ch][pr * 2 + 1][1] = r[3];
                }
            }
            #pragma unroll
            for (int cc = 0; cc < 3; cc++) {
                uint32_t af[2][2][4];
                #pragma unroll
                for (int p = 0; p < 2; p++) {
                    int ch = cc * 2 + p;
                    #pragma unroll
                    for (int f = 0; f < 2; f++)
                        ldsm4(sa + ch * A_CH_BYTES
                              + (wm * 32 + f * 16 + arow) * APITCH + s * 32 + aksel, af[p][f]);
                }
                const int bch = (cc == 2) ? 2 : 0;
                // term-outermost: same-acc reuse distance = 8 independent MMAs
                #pragma unroll
                for (int t = 0; t < 3; t++) {
                    const int asel = (t == 2) ? 1 : 0;
                    const int bsel = (t == 1) ? 1 : 0;
                    #pragma unroll
                    for (int f = 0; f < 2; f++)
                        #pragma unroll
                        for (int g = 0; g < 4; g++)
                            mma16816(acc[cc][f][g], af[asel][f], bf[bch + bsel][g]);
                }
            }
        }
        __syncthreads();
    }

    const int colBase = n0 + wn * 32 + (lane & 3) * 2;
    const int rowBase = m0 + wm * 32 + (lane >> 2);
    #pragma unroll
    for (int f = 0; f < 2; f++) {
        #pragma unroll
        for (int g = 0; g < 4; g++) {
            int col = colBase + g * 8;
            float2 bb = *(const float2*)(bias + col);
            #pragma unroll
            for (int half = 0; half < 2; half++) {
                int row = rowBase + f * 16 + half * 8;
                size_t gi = (size_t)row * Nmat + col;
                int d = half * 2;
                float v0 = acc[0][f][g][d], v1 = acc[0][f][g][d + 1];
                float c0 = acc[1][f][g][d], c1 = acc[1][f][g][d + 1];
                float r0 = acc[2][f][g][d], r1 = acc[2][f][g][d + 1];
                *(float2*)(Yv + gi) = make_float2(v0 + bb.x, v1 + bb.y);
                *(float2*)(Yl + gi) = make_float2(c0 - r0 + bb.x, c1 - r1 + bb.y);
                *(float2*)(Yu + gi) = make_float2(c0 + r0 + bb.x, c1 + r1 + bb.y);
            }
        }
    }
}

// ============================================================================
// Shared tiling constants for K2/K4 multi-pass MMA kernels
// ============================================================================
#define PITCH2 144
#define A_CH2 (128 * PITCH2)
#define B_CH2 (64 * PITCH2)
#define STAGE2 (2 * A_CH2 + 2 * B_CH2)    /* 55296 */
#define SMEM2  (2 * STAGE2)               /* 110592 */

#define MP_COMPUTE(SA, ACC)                                                    \
    _Pragma("unroll")                                                          \
    for (int s = 0; s < 4; s++) {                                              \
        uint32_t af[2][2][4];                                                  \
        _Pragma("unroll")                                                      \
        for (int hl = 0; hl < 2; hl++)                                         \
            _Pragma("unroll")                                                  \
            for (int f = 0; f < 2; f++)                                        \
                ldsm4((SA) + hl * A_CH2                                        \
                      + (wm * 32 + f * 16 + arow) * PITCH2 + s * 32 + aksel,   \
                      af[hl][f]);                                              \
        uint32_t bfr[2][4][2];                                                 \
        _Pragma("unroll")                                                      \
        for (int hl = 0; hl < 2; hl++)                                         \
            _Pragma("unroll")                                                  \
            for (int pr = 0; pr < 2; pr++) {                                   \
                uint32_t r[4];                                                 \
                ldsm4((SA) + 2 * A_CH2 + hl * B_CH2                            \
                      + (wn * 32 + pr * 16 + brow) * PITCH2 + s * 32 + bksel,  \
                      r);                                                      \
                bfr[hl][pr * 2 + 0][0] = r[0]; bfr[hl][pr * 2 + 0][1] = r[1];  \
                bfr[hl][pr * 2 + 1][0] = r[2]; bfr[hl][pr * 2 + 1][1] = r[3];  \
            }                                                                  \
        _Pragma("unroll")                                                      \
        for (int t = 0; t < 3; t++) {                                          \
            const int asel = (t == 2) ? 1 : 0;                                 \
            const int bsel = (t == 1) ? 1 : 0;                                 \
            _Pragma("unroll")                                                  \
            for (int f = 0; f < 2; f++)                                        \
                _Pragma("unroll")                                              \
                for (int g = 0; g < 4; g++)                                    \
                    mma16816(ACC[f][g], af[asel][f], bfr[bsel][g]);            \
        }                                                                      \
    }

// ============================================================================
// K2 (HMMA): interval scores via 9 clamp-product passes, K=64 each.
// lb = p(ql)@p(kl) + p(qu)@n(kl) + n(ql)@p(ku) + n(qu)@n(ku); ub symmetric.
// ============================================================================
__global__ void __launch_bounds__(256, 1) scores_mma(
    const __nv_bfloat16* __restrict__ qa, const __nv_bfloat16* __restrict__ ka,
    float* __restrict__ Sv, float* __restrict__ Sl, float* __restrict__ Su)
{
    extern __shared__ char smem[];
    const uint32_t sbase = smem_u32(smem);
    const int tid = threadIdx.x, warp = tid >> 5, lane = tid & 31;
    const int wm = warp >> 1, wn = warp & 1;
    const int bh = blockIdx.z, m0 = blockIdx.y * 128, n0 = blockIdx.x * 64;
    const size_t CH = (size_t)NBH * SSEQ * DHEAD;
    const __nv_bfloat16* Ab = qa + (size_t)bh * SSEQ * DHEAD;
    const __nv_bfloat16* Bb = ka + (size_t)bh * SSEQ * DHEAD;

    const int cPA[10] = {0, 1, 2, 3, 4, 2, 1, 4, 3, 0};
    const int cPB[10] = {0, 1, 2, 3, 4, 3, 4, 1, 2, 0};

    float acc0[2][4][4] = {}, acc1[2][4][4] = {}, acc2[2][4][4] = {};

    auto load_pass = [&](int stage, int pa, int pb) {
        const uint32_t sa = sbase + stage * STAGE2;
        #pragma unroll
        for (int t = 0; t < 8; t++) {
            int u = tid + t * 256;
            int hl = u >> 10, rem = u & 1023, row = rem >> 3, c8 = rem & 7;
            cp16(sa + hl * A_CH2 + row * PITCH2 + c8 * 16,
                 Ab + (size_t)(2 * pa + hl) * CH + (size_t)(m0 + row) * DHEAD + c8 * 8);
        }
        #pragma unroll
        for (int t = 0; t < 4; t++) {
            int u = tid + t * 256;
            int hl = u >> 9, rem = u & 511, row = rem >> 3, c8 = rem & 7;
            cp16(sa + 2 * A_CH2 + hl * B_CH2 + row * PITCH2 + c8 * 16,
                 Bb + (size_t)(2 * pb + hl) * CH + (size_t)(n0 + row) * DHEAD + c8 * 8);
        }
        cp_commit();
    };

    const int arow = lane & 15;
    const int aksel = (lane >> 4) * 16;
    const int brow = ((lane >> 4) & 1) * 8 + (lane & 7);
    const int bksel = ((lane >> 3) & 1) * 16;

    load_pass(0, cPA[0], cPB[0]);

#define SC_PASS(P, ACC)                                                        \
    do {                                                                       \
        if ((P) + 1 < 9) { load_pass(((P) + 1) & 1, cPA[(P) + 1], cPB[(P) + 1]); cp_wait<1>(); } \
        else { cp_wait<0>(); }                                                 \
        __syncthreads();                                                       \
        const uint32_t sa_ = sbase + ((P) & 1) * STAGE2;                       \
        MP_COMPUTE(sa_, ACC);                                                  \
        __syncthreads();                                                       \
    } while (0)

    SC_PASS(0, acc0);
    SC_PASS(1, acc1); SC_PASS(2, acc1); SC_PASS(3, acc1); SC_PASS(4, acc1);
    SC_PASS(5, acc2); SC_PASS(6, acc2); SC_PASS(7, acc2); SC_PASS(8, acc2);
#undef SC_PASS

    const size_t sb = (size_t)bh * SSEQ * SSEQ;
    const int colBase = n0 + wn * 32 + (lane & 3) * 2;
    const int rowBase = m0 + wm * 32 + (lane >> 2);
    #pragma unroll
    for (int f = 0; f < 2; f++) {
        #pragma unroll
        for (int g = 0; g < 4; g++) {
            int col = colBase + g * 8;
            #pragma unroll
            for (int half = 0; half < 2; half++) {
                int row = rowBase + f * 16 + half * 8;
                size_t gi = sb + (size_t)row * SSEQ + col;
                int d = half * 2;
                *(float2*)(Sv + gi) = make_float2(acc0[f][g][d], acc0[f][g][d + 1]);
                *(float2*)(Sl + gi) = make_float2(acc1[f][g][d], acc1[f][g][d + 1]);
                *(float2*)(Su + gi) = make_float2(acc2[f][g][d], acc2[f][g][d + 1]);
            }
        }
    }
}

// ============================================================================
// K3: IBP softmax; reads fp32 scores, emits bf16-split (pv,pc,pr) for K4
// ============================================================================
__global__ void __launch_bounds__(256) ibp_softmax_kernel(
    const float* __restrict__ Sv, const float* __restrict__ Sl, const float* __restrict__ Su,
    __nv_bfloat16* __restrict__ p6)
{
    const int row  = blockIdx.x * 8 + (threadIdx.x >> 5);
    const int lane = threadIdx.x & 31;
    size_t base = (size_t)row * SSEQ + lane;
    const size_t CHP = (size_t)NBH * SSEQ * SSEQ;

    float v[16], l[16], u[16];
    #pragma unroll
    for (int t = 0; t < 16; t++) {
        v[t] = Sv[base + t * 32];
        l[t] = Sl[base + t * 32];
        u[t] = Su[base + t * 32];
    }
    float mu = -INFINITY, mv = -INFINITY;
    #pragma unroll
    for (int t = 0; t < 16; t++) { mu = fmaxf(mu, u[t]); mv = fmaxf(mv, v[t]); }
    #pragma unroll
    for (int o = 16; o > 0; o >>= 1) {
        mu = fmaxf(mu, __shfl_xor_sync(0xFFFFFFFFu, mu, o));
        mv = fmaxf(mv, __shfl_xor_sync(0xFFFFFFFFu, mv, o));
    }
    float sumv = 0.0f, suml = 0.0f, sumu = 0.0f;
    #pragma unroll
    for (int t = 0; t < 16; t++) {
        v[t] = __expf(v[t] - mv);
        l[t] = __expf(l[t] - mu);
        u[t] = __expf(u[t] - mu);
        sumv += v[t]; suml += l[t]; sumu += u[t];
    }
    #pragma unroll
    for (int o = 16; o > 0; o >>= 1) {
        sumv += __shfl_xor_sync(0xFFFFFFFFu, sumv, o);
        suml += __shfl_xor_sync(0xFFFFFFFFu, suml, o);
        sumu += __shfl_xor_sync(0xFFFFFFFFu, sumu, o);
    }
    #pragma unroll
    for (int t = 0; t < 16; t++) {
        float pv = v[t] / sumv;
        float pl = l[t] / (sumu - u[t] + l[t]);
        float pu = u[t] / (suml - l[t] + u[t]);
        pl = fminf(fmaxf(pl, 0.0f), 1.0f);
        pu = fminf(fmaxf(pu, 0.0f), 1.0f);
        float pc = 0.5f * (pl + pu), pr = 0.5f * (pu - pl);
        size_t gi = base + t * 32;
        __nv_bfloat16 hi, lo;
        split_bf16(pv, hi, lo); p6[gi] = hi;           p6[CHP + gi] = lo;
        split_bf16(pc, hi, lo); p6[2 * CHP + gi] = hi; p6[3 * CHP + gi] = lo;
        split_bf16(pr, hi, lo); p6[4 * CHP + gi] = hi; p6[5 * CHP + gi] = lo;
    }
}

// ============================================================================
// K4 (HMMA): O = P @ V via 5 passes (pv@Vv | pc@Vl, pr@(-|Vl|) | pc@Vu, pr@|Vu|)
// K=512 per pass in 8 chunks of 64. Epilogue emits o6 splits merged [B,S,E].
// ============================================================================
__global__ void __launch_bounds__(256, 1) pv_mma(
    const __nv_bfloat16* __restrict__ p6, const __nv_bfloat16* __restrict__ vt,
    __nv_bfloat16* __restrict__ O6)
{
    extern __shared__ char smem[];
    const uint32_t sbase = smem_u32(smem);
    const int tid = threadIdx.x, warp = tid >> 5, lane = tid & 31;
    const int wm = warp >> 1, wn = warp & 1;
    const int bh = blockIdx.z, m0 = blockIdx.y * 128;
    const size_t CHP = (size_t)NBH * SSEQ * SSEQ;
    const size_t CHV = (size_t)NBH * DHEAD * SSEQ;
    const __nv_bfloat16* Ab = p6 + (size_t)bh * SSEQ * SSEQ;
    const __nv_bfloat16* Bb = vt + (size_t)bh * DHEAD * SSEQ;

    const int vPA[6] = {0, 1, 2, 1, 2, 0};
    const int vPB[6] = {0, 1, 2, 3, 4, 0};

    float acc0[2][4][4] = {}, acc1[2][4][4] = {}, acc2[2][4][4] = {};

    auto load_st = [&](int stage, int pa, int pb, int kc) {
        const uint32_t sa = sbase + stage * STAGE2;
        #pragma unroll
        for (int t = 0; t < 8; t++) {
            int u = tid + t * 256;
            int hl = u >> 10, rem = u & 1023, row = rem >> 3, c8 = rem & 7;
            cp16(sa + hl * A_CH2 + row * PITCH2 + c8 * 16,
                 Ab + (size_t)(2 * pa + hl) * CHP + (size_t)(m0 + row) * SSEQ + kc * 64 + c8 * 8);
        }
        #pragma unroll
        for (int t = 0; t < 4; t++) {
            int u = tid + t * 256;
            int hl = u >> 9, rem = u & 511, row = rem >> 3, c8 = rem & 7;
            cp16(sa + 2 * A_CH2 + hl * B_CH2 + row * PITCH2 + c8 * 16,
                 Bb + (size_t)(2 * pb + hl) * CHV + (size_t)row * SSEQ + kc * 64 + c8 * 8);
        }
        cp_commit();
    };

    const int arow = lane & 15;
    const int aksel = (lane >> 4) * 16;
    const int brow = ((lane >> 4) & 1) * 8 + (lane & 7);
    const int bksel = ((lane >> 3) & 1) * 16;

    load_st(0, vPA[0], vPB[0], 0);

#define PV_PASS(P, ACC)                                                        \
    do {                                                                       \
        _Pragma("unroll")                                                      \
        for (int kc = 0; kc < 8; kc++) {                                       \
            const int st = (P) * 8 + kc;                                       \
            if (st + 1 < 40) {                                                 \
                const int nst = st + 1;                                        \
                load_st(nst & 1, vPA[nst >> 3], vPB[nst >> 3], nst & 7);       \
                cp_wait<1>();                                                  \
            } else { cp_wait<0>(); }                                           \
            __syncthreads();                                                   \
            const uint32_t sa_ = sbase + (st & 1) * STAGE2;                    \
            MP_COMPUTE(sa_, ACC);                                              \
            __syncthreads();                                                   \
        }                                                                      \
    } while (0)

    PV_PASS(0, acc0);
    PV_PASS(1, acc1); PV_PASS(2, acc1);
    PV_PASS(3, acc2); PV_PASS(4, acc2);
#undef PV_PASS

    // epilogue: lb=acc1, ub=acc2 -> (v,c,r) bf16 splits in merged [B,S,E]
    const int b = bh >> 4, h = bh & 15;
    const size_t OS = (size_t)MROWS * EE;
    const int colBase = wn * 32 + (lane & 3) * 2;
    const int rowBase = m0 + wm * 32 + (lane >> 2);
    #pragma unroll
    for (int f = 0; f < 2; f++) {
        #pragma unroll
        for (int g = 0; g < 4; g++) {
            int col = colBase + g * 8;
            #pragma unroll
            for (int half = 0; half < 2; half++) {
                int row = rowBase + f * 16 + half * 8;
                #pragma unroll
                for (int e = 0; e < 2; e++) {
                    int d = half * 2 + e;
                    float v = acc0[f][g][d];
                    float lb = acc1[f][g][d], ub = acc2[f][g][d];
                    float c = 0.5f * (lb + ub), r = 0.5f * (ub - lb);
                    size_t gi = (size_t)(b * SSEQ + row) * EE + h * DHEAD + col + e;
                    __nv_bfloat16 hi, lo;
                    split_bf16(v, hi, lo); O6[gi] = hi;          O6[OS + gi] = lo;
                    split_bf16(c, hi, lo); O6[2 * OS + gi] = hi; O6[3 * OS + gi] = lo;
                    split_bf16(r, hi, lo); O6[4 * OS + gi] = hi; O6[5 * OS + gi] = lo;
                }
            }
        }
    }
}

// ============================================================================
// Launch
// ============================================================================
extern "C" void kernel_launch(void* const* d_in, const int* in_sizes, int n_in,
                              void* d_out, int out_size) {
    const float* xv = (const float*)d_in[0];
    const float* xl = (const float*)d_in[1];
    const float* xu = (const float*)d_in[2];
    const float* Wi = (const float*)d_in[3];
    const float* bi = (const float*)d_in[4];
    const float* Wo = (const float*)d_in[5];
    const float* bo = (const float*)d_in[6];
    float* out = (float*)d_out;

    float *qv, *ql, *qu, *sv, *sl, *su;
    __nv_bfloat16 *x6, *o6, *wi4, *wo4, *qa, *ka, *p6, *vt;
    cudaGetSymbolAddress((void**)&qv, g_qkv_v);
    cudaGetSymbolAddress((void**)&ql, g_qkv_l);
    cudaGetSymbolAddress((void**)&qu, g_qkv_u);
    cudaGetSymbolAddress((void**)&sv, g_s_v);
    cudaGetSymbolAddress((void**)&sl, g_s_l);
    cudaGetSymbolAddress((void**)&su, g_s_u);
    cudaGetSymbolAddress((void**)&x6, g_x6);
    cudaGetSymbolAddress((void**)&o6, g_o6);
    cudaGetSymbolAddress((void**)&wi4, g_wi4);
    cudaGetSymbolAddress((void**)&wo4, g_wo4);
    cudaGetSymbolAddress((void**)&qa, g_qa);
    cudaGetSymbolAddress((void**)&ka, g_ka);
    cudaGetSymbolAddress((void**)&p6, g_p6);
    cudaGetSymbolAddress((void**)&vt, g_vt);

    cudaFuncSetAttribute(ibp_gemm_mma, cudaFuncAttributeMaxDynamicSharedMemorySize, GEMM_SMEM);
    cudaFuncSetAttribute(scores_mma,   cudaFuncAttributeMaxDynamicSharedMemorySize, SMEM2);
    cudaFuncSetAttribute(pv_mma,       cudaFuncAttributeMaxDynamicSharedMemorySize, SMEM2);

    dim3 blk(256);

    // prep: bf16 splits of x and weights
    prep_x_kernel<<<(MROWS * EE) / 256, blk>>>(xv, xl, xu, x6);
    prep_w_kernel<<<dim3(E3 / 32, EE / 32), blk>>>(Wi, wi4, EE, E3);
    prep_w_kernel<<<dim3(EE / 32, EE / 32), blk>>>(Wo, wo4, EE, EE);

    // K1 (HMMA): qkv = ibp_linear(x, in_proj)
    ibp_gemm_mma<<<dim3(E3 / BN, MROWS / BM), blk, GEMM_SMEM>>>(
        x6, wi4, bi, qv, ql, qu, EE, E3);

    // prep clamp-split q/k channels and transposed V channels
    prep_qk_kernel<<<(NBH * SSEQ * DHEAD) / 256, blk>>>(qv, ql, qu, qa, ka);
    prep_vt_kernel<<<dim3(SSEQ / 32, DHEAD / 32, NBH), blk>>>(qv, ql, qu, vt);

    // K2 (HMMA): interval scores
    scores_mma<<<dim3(SSEQ / 64, SSEQ / 128, NBH), blk, SMEM2>>>(
        qa, ka, sv, sl, su);

    // K3: IBP softmax -> bf16 splits of (pv, pc, pr)
    ibp_softmax_kernel<<<(NBH * SSEQ) / 8, blk>>>(sv, sl, su, p6);

    // K4 (HMMA): O = P @ V -> o6 splits
    pv_mma<<<dim3(1, SSEQ / 128, NBH), blk, SMEM2>>>(p6, vt, o6);

    // K5 (HMMA): y = ibp_linear(O, out_proj) -> d_out [3][2048][1024]
    ibp_gemm_mma<<<dim3(EE / BN, MROWS / BM), blk, GEMM_SMEM>>>(
        o6, wo4, bo, out, out + (size_t)MROWS * EE, out + 2 * (size_t)MROWS * EE,
        EE, EE);
}